// round 10
// baseline (speedup 1.0000x reference)
#include <cuda_runtime.h>
#include <cuda_fp16.h>
#include <math.h>
#include <stdint.h>

// Problem constants
#define B_  16
#define T_  4096
#define D_  1024
#define U_  1024
#define M_  (B_ * T_)   // 65536 rows

// ---------------------------------------------------------------------------
// Device-global scratch (no allocations allowed)
// ---------------------------------------------------------------------------
__device__ __half g_Xhi[(size_t)M_ * D_];   // 128 MiB  (fp16 of enc)
__device__ __half g_Whi[(size_t)U_ * D_];   // W2^T [u][d] fp16
__device__ float g_hpb[B_ * U_];
__device__ float g_score[M_];

// ---------------------------------------------------------------------------
// Helpers
// ---------------------------------------------------------------------------
__device__ __forceinline__ uint32_t smem_u32(const void* p) {
    uint32_t a;
    asm("{ .reg .u64 t; cvta.to.shared.u64 t, %1; cvt.u32.u64 %0, t; }" : "=r"(a) : "l"(p));
    return a;
}
#define CP_ASYNC16(dst, src) \
    asm volatile("cp.async.cg.shared.global [%0], [%1], 16;" :: "r"(dst), "l"(src))
#define CP_COMMIT() asm volatile("cp.async.commit_group;" ::: "memory")
#define CP_WAIT1()  asm volatile("cp.async.wait_group 1;" ::: "memory")

__device__ __forceinline__ void ldm_x4(uint32_t* r, uint32_t addr) {
    asm volatile("ldmatrix.sync.aligned.m8n8.x4.shared.b16 {%0,%1,%2,%3}, [%4];"
                 : "=r"(r[0]), "=r"(r[1]), "=r"(r[2]), "=r"(r[3]) : "r"(addr));
}
// fp16-ACCUMULATE mma: D,C are 2x b32 regs (4 halves). Hypothesis: 2x rate
// vs f32-accum on sm_103a legacy tensor path.
__device__ __forceinline__ void mma_f16acc(uint32_t* c, const uint32_t* a,
                                           const uint32_t* b) {
    asm volatile(
        "mma.sync.aligned.m16n8k16.row.col.f16.f16.f16.f16 "
        "{%0,%1}, {%2,%3,%4,%5}, {%6,%7}, {%0,%1};"
        : "+r"(c[0]), "+r"(c[1])
        : "r"(a[0]), "r"(a[1]), "r"(a[2]), "r"(a[3]), "r"(b[0]), "r"(b[1]));
}

// FMA-only fast tanh (abs err ~1e-6); avoids MUFU entirely.
__device__ __forceinline__ float fast_tanh(float x) {
    float ax = fabsf(x);
    float t = fminf(ax * 2.885390082f, 30.0f);     // 2|x|*log2(e)
    float nt = -t;
    float fi = floorf(nt);
    float f = nt - fi;                              // [0,1)
    float p =              1.5253232e-5f;
    p = fmaf(p, f, 1.5403530e-4f);
    p = fmaf(p, f, 1.3333558e-3f);
    p = fmaf(p, f, 9.6181291e-3f);
    p = fmaf(p, f, 5.5504109e-2f);
    p = fmaf(p, f, 2.4022651e-1f);
    p = fmaf(p, f, 6.9314718e-1f);
    p = fmaf(p, f, 1.0f);
    int ei = (int)fi;                               // [-30, 0]
    float e = __int_as_float((ei + 127) << 23) * p; // 2^nt = e^{-2|x|}
    float d = 1.0f + e;
    float r = __int_as_float(0x7EF311C3u - __float_as_int(d));
    r = r * (2.0f - d * r);
    r = r * (2.0f - d * r);
    r = r * (2.0f - d * r);
    float y = (1.0f - e) * r;
    return copysignf(y, x);
}

// ---------------------------------------------------------------------------
// Kernel A: enc fp32 -> fp16
// ---------------------------------------------------------------------------
__global__ void convert_x_kernel(const float* __restrict__ X) {
    size_t i = ((size_t)blockIdx.x * 256 + threadIdx.x) * 8;
    float4 a = *(const float4*)(X + i);
    float4 b = *(const float4*)(X + i + 4);
    float v[8] = {a.x, a.y, a.z, a.w, b.x, b.y, b.z, b.w};
    __half hi[8];
    #pragma unroll
    for (int j = 0; j < 8; j++) hi[j] = __float2half_rn(v[j]);
    *(uint4*)(g_Xhi + i) = *(uint4*)hi;
}

// ---------------------------------------------------------------------------
// Kernel B: transpose W2 [d][u] -> [u][d] fp16
// ---------------------------------------------------------------------------
__global__ void convert_w_kernel(const float* __restrict__ W2) {
    __shared__ float tile[32][33];
    const int u0 = blockIdx.x * 32, d0 = blockIdx.y * 32;
    const int tx = threadIdx.x, ty = threadIdx.y;           // (32, 8)
    #pragma unroll
    for (int j = 0; j < 32; j += 8)
        tile[ty + j][tx] = W2[(size_t)(d0 + ty + j) * U_ + u0 + tx];
    __syncthreads();
    #pragma unroll
    for (int j = 0; j < 32; j += 8)
        g_Whi[(size_t)(u0 + ty + j) * D_ + d0 + tx] =
            __float2half_rn(tile[tx][ty + j]);
}

// ---------------------------------------------------------------------------
// Kernel C: hpb[b,u] = h@W1 + b1 + b2
// ---------------------------------------------------------------------------
__global__ void hproj_kernel(const float* __restrict__ h,
                             const float* __restrict__ W1,
                             const float* __restrict__ b1,
                             const float* __restrict__ b2) {
    __shared__ float hs[D_];
    const int b = blockIdx.y;
    const int u = blockIdx.x * 256 + threadIdx.x;
    for (int i = threadIdx.x; i < D_; i += 256) hs[i] = h[b * D_ + i];
    __syncthreads();
    float acc = 0.f;
    #pragma unroll 8
    for (int d = 0; d < D_; d++) acc = fmaf(hs[d], W1[d * U_ + u], acc);
    g_hpb[b * U_ + u] = acc + b1[u] + b2[u];
}

// ---------------------------------------------------------------------------
// Kernel D: score GEMM via mma.sync fp16 with fp16 ACCUMULATORS (windowed:
// fp16 acc lives across one K=64 stage, flushed to fp32 master each stage).
// Grid = 2048 (row-block x u-pass), atomicAdd partial row sums.
// 256 threads / 8 warps, 64x64 warp tiles, 3-stage cp.async pipeline.
// ---------------------------------------------------------------------------
#define ROWB     144                      // 128 B data + 16 B pad
#define A_TILE   (128 * ROWB)             // 18432
#define B_TILE   (256 * ROWB)             // 36864
#define STAGE_SZ (A_TILE + B_TILE)        // 55296
#define OFF_B    A_TILE
#define NSTAGE   3
#define OFF_VH   (NSTAGE * STAGE_SZ)      // 165888
#define OFF_RED  (OFF_VH + 2048)
#define SK_SMEM  (OFF_RED + 4096)         // 172032

__global__ void __launch_bounds__(256, 1)
score_kernel(const float* __restrict__ V) {
    extern __shared__ char smem[];
    const uint32_t sb = smem_u32(smem);
    const int tid = threadIdx.x;
    const int lane = tid & 31;
    const int wid = tid >> 5;
    const int warp_m = wid >> 2;        // 0..1  (64 rows each)
    const int warp_n = wid & 3;         // 0..3  (64 cols each)
    const int row0 = (blockIdx.x >> 2) * 128;   // row block
    const int n0   = (blockIdx.x & 3) * 256;    // u-pass
    const int b = row0 >> 12;

    float* vbuf = (float*)(smem + OFF_VH);
    float* hbuf = (float*)(smem + OFF_VH + 1024);
    float* red  = (float*)(smem + OFF_RED);

    const uint32_t a_loff = (uint32_t)((lane & 15) * ROWB + (lane >> 4) * 16);
    const uint32_t b_loff = (uint32_t)(((lane & 7) + ((lane >> 4) << 3)) * ROWB
                                       + ((lane >> 3) & 1) * 16);

    vbuf[tid] = V[n0 + tid];
    hbuf[tid] = g_hpb[b * U_ + n0 + tid];

    float acc[4][8][4];                // fp32 master accumulators
    #pragma unroll
    for (int mt = 0; mt < 4; mt++)
        #pragma unroll
        for (int nt = 0; nt < 8; nt++)
            #pragma unroll
            for (int c = 0; c < 4; c++) acc[mt][nt][c] = 0.f;

    // ---- stage loader (K chunk of 64 into stage s), 256 threads ----
    auto load_stage = [&](int s, int k0) {
        const uint32_t stg = sb + s * STAGE_SZ;
        #pragma unroll
        for (int it = 0; it < 4; it++) {       // A: 128 rows x 8 chunks
            const int task = tid + it * 256;
            const int r = task >> 3, c = task & 7;
            const __half* src = g_Xhi + (size_t)(row0 + r) * D_ + k0 + c * 8;
            CP_ASYNC16(stg + r * ROWB + c * 16, src);
        }
        #pragma unroll
        for (int it = 0; it < 8; it++) {       // B: 256 rows x 8 chunks
            const int task = tid + it * 256;
            const int r = task >> 3, c = task & 7;
            const __half* src = g_Whi + (size_t)(n0 + r) * D_ + k0 + c * 8;
            CP_ASYNC16(stg + OFF_B + r * ROWB + c * 16, src);
        }
    };

    load_stage(0, 0);   CP_COMMIT();
    load_stage(1, 64);  CP_COMMIT();

    #pragma unroll 1
    for (int kc = 0; kc < 16; kc++) {
        CP_WAIT1();
        __syncthreads();
        if (kc + 2 < 16) load_stage((kc + 2) % NSTAGE, (kc + 2) * 64);
        CP_COMMIT();

        const uint32_t stg = sb + (kc % NSTAGE) * STAGE_SZ;
        const uint32_t aBase = stg + warp_m * 64 * ROWB + a_loff;
        const uint32_t bBase = stg + OFF_B + warp_n * 64 * ROWB + b_loff;

        // fp16 working accumulators for this K=64 window
        uint32_t hacc[4][8][2];
        #pragma unroll
        for (int mt = 0; mt < 4; mt++)
            #pragma unroll
            for (int nt = 0; nt < 8; nt++)
                hacc[mt][nt][0] = hacc[mt][nt][1] = 0u;

        #pragma unroll
        for (int k16 = 0; k16 < 4; k16++) {
            const uint32_t ko = k16 * 32;      // 16 fp16 = 32 bytes
            uint32_t af[4][4], bf[4][4];
            #pragma unroll
            for (int i = 0; i < 4; i++)
                ldm_x4(bf[i], bBase + i * 16 * ROWB + ko);
            #pragma unroll
            for (int mt = 0; mt < 4; mt++)
                ldm_x4(af[mt], aBase + mt * 16 * ROWB + ko);
            #pragma unroll
            for (int mt = 0; mt < 4; mt++)
                #pragma unroll
                for (int nt = 0; nt < 8; nt++)
                    mma_f16acc(hacc[mt][nt], af[mt], &bf[nt >> 1][(nt & 1) * 2]);
        }

        // ---- flush window into fp32 master ----
        #pragma unroll
        for (int mt = 0; mt < 4; mt++)
            #pragma unroll
            for (int nt = 0; nt < 8; nt++) {
                const float2 lo = __half22float2(*(const __half2*)&hacc[mt][nt][0]);
                const float2 hi = __half22float2(*(const __half2*)&hacc[mt][nt][1]);
                acc[mt][nt][0] += lo.x;
                acc[mt][nt][1] += lo.y;
                acc[mt][nt][2] += hi.x;
                acc[mt][nt][3] += hi.y;
            }
    }

    // ---- epilogue: fold tanh + V into per-row partials ----
    float rowsum8[8];
    #pragma unroll
    for (int j = 0; j < 8; j++) rowsum8[j] = 0.f;
    #pragma unroll
    for (int mt = 0; mt < 4; mt++)
        #pragma unroll
        for (int nt = 0; nt < 8; nt++)
            #pragma unroll
            for (int c = 0; c < 4; c++) {
                const int ul = warp_n * 64 + nt * 8 + (lane & 3) * 2 + (c & 1);
                const float s = acc[mt][nt][c] + hbuf[ul];
                rowsum8[mt * 2 + (c >> 1)] =
                    fmaf(vbuf[ul], fast_tanh(s), rowsum8[mt * 2 + (c >> 1)]);
            }

    // cross-thread reduction: quad-shfl, then 4 warp_n slices via smem
    #pragma unroll
    for (int j = 0; j < 8; j++) {
        float v = rowsum8[j];
        v += __shfl_xor_sync(0xffffffffu, v, 1);
        v += __shfl_xor_sync(0xffffffffu, v, 2);
        if ((lane & 3) == 0) {
            const int r = warp_m * 64 + (j >> 1) * 16 + (lane >> 2) + 8 * (j & 1);
            red[r * 4 + warp_n] = v;
        }
    }
    __syncthreads();
    if (tid < 128)
        atomicAdd(&g_score[row0 + tid],
                  red[tid * 4 + 0] + red[tid * 4 + 1]
                + red[tid * 4 + 2] + red[tid * 4 + 3]);
}

// ---------------------------------------------------------------------------
// Kernel E: softmax over T per batch (bv constant -> softmax-invariant)
// ---------------------------------------------------------------------------
__global__ void softmax_kernel(float* __restrict__ wout) {
    const int b = blockIdx.x;
    const float* s = g_score + b * T_;
    float* w = wout + b * T_;
    __shared__ float red[256];
    const int tid = threadIdx.x;

    float mx = -INFINITY;
    for (int t = tid; t < T_; t += 256) mx = fmaxf(mx, s[t]);
    red[tid] = mx; __syncthreads();
    for (int o = 128; o > 0; o >>= 1) {
        if (tid < o) red[tid] = fmaxf(red[tid], red[tid + o]);
        __syncthreads();
    }
    mx = red[0]; __syncthreads();

    float sum = 0.f;
    for (int t = tid; t < T_; t += 256) {
        const float e = expf(s[t] - mx);
        w[t] = e;
        sum += e;
    }
    red[tid] = sum; __syncthreads();
    for (int o = 128; o > 0; o >>= 1) {
        if (tid < o) red[tid] += red[tid + o];
        __syncthreads();
    }
    const float inv = 1.f / red[0];
    for (int t = tid; t < T_; t += 256) w[t] *= inv;
}

// ---------------------------------------------------------------------------
// Kernel F: context[b,d] = sum_t w[b,t] * enc_fp16[b,t,d]
// ---------------------------------------------------------------------------
__global__ void context_kernel(const float* __restrict__ w,
                               float* __restrict__ ctx) {
    const int b  = blockIdx.y;
    const int t0 = blockIdx.x * 128;
    const int tid = threadIdx.x;
    float c[4] = {0.f, 0.f, 0.f, 0.f};
    for (int t = t0; t < t0 + 128; t++) {
        const float wt = w[b * T_ + t];
        const __half* row = g_Xhi + ((size_t)b * T_ + t) * D_;
        #pragma unroll
        for (int j = 0; j < 4; j++)
            c[j] = fmaf(wt, __half2float(row[tid + j * 256]), c[j]);
    }
    #pragma unroll
    for (int j = 0; j < 4; j++)
        atomicAdd(&ctx[b * D_ + tid + j * 256], c[j]);
}

// ---------------------------------------------------------------------------
extern "C" void kernel_launch(void* const* d_in, const int* in_sizes, int n_in,
                              void* d_out, int out_size) {
    const float* h   = (const float*)d_in[0];  // [B, D]
    const float* enc = (const float*)d_in[1];  // [B, T, D]
    const float* W1  = (const float*)d_in[2];  // [D, U]
    const float* b1  = (const float*)d_in[3];  // [U]
    const float* W2  = (const float*)d_in[4];  // [D, U]
    const float* b2  = (const float*)d_in[5];  // [U]
    const float* V   = (const float*)d_in[6];  // [U, 1]
    // d_in[7] = bv: softmax-invariant constant, unused.

    float* out = (float*)d_out;
    float* ctx = out;             // [B, D]
    float* wts = out + B_ * D_;   // [B, T, 1]

    cudaFuncSetAttribute(score_kernel,
                         cudaFuncAttributeMaxDynamicSharedMemorySize, SK_SMEM);

    void* scorePtr = nullptr;
    cudaGetSymbolAddress(&scorePtr, g_score);

    cudaMemsetAsync(ctx, 0, (size_t)B_ * D_ * sizeof(float));
    cudaMemsetAsync(scorePtr, 0, (size_t)M_ * sizeof(float));

    convert_x_kernel<<<(M_ * D_) / (256 * 8), 256>>>(enc);
    convert_w_kernel<<<dim3(32, 32), dim3(32, 8)>>>(W2);
    hproj_kernel<<<dim3(U_ / 256, B_), 256>>>(h, W1, b1, b2);
    score_kernel<<<4 * (M_ / 128), 256, SK_SMEM>>>(V);
    softmax_kernel<<<B_, 256>>>(wts);
    context_kernel<<<dim3(T_ / 128, B_), 256>>>(wts, ctx);
}